// round 7
// baseline (speedup 1.0000x reference)
#include <cuda_runtime.h>

// Batched Kalman filter: B=262144, N=8, M=4, fp32.
// 2 threads per batch; thread s (= tid&1) owns rows {s, s+2, s+4, s+6}.
// Pair exchange through smem (same warp -> __syncwarp). All gmem coalesced
// float4 via smem staging. Uses P_pred symmetry (HP = A^T).
// Outputs flat: x_new[B,8], P_new[B,8,8], K[B,8,4].

constexpr int BT  = 262144;
constexpr int TPB = 64;
constexpr int G   = 32;          // batches per block (2 threads each)
constexpr float EPS = 1e-6f;

constexpr int SF  = 68;          // 64-float mats
constexpr int SH  = 36;          // 32-float mats
constexpr int SR  = 20;          // 16-float mats
constexpr int SXZ = 12;          // x[8] ++ z[4] combined

template<int E, int S>
__device__ __forceinline__ void stage_in(float* sm, const float* __restrict__ gp,
                                         int b0, int tid) {
    const float4* g4 = reinterpret_cast<const float4*>(gp + (size_t)b0 * E);
    constexpr int T4 = G * E / 4;
#pragma unroll
    for (int i = tid; i < T4; i += TPB) {
        float4 v = g4[i];
        int e = i * 4;
        *reinterpret_cast<float4*>(sm + (e / E) * S + (e % E)) = v;
    }
}

template<int E, int S>
__device__ __forceinline__ void stage_out(float* __restrict__ gp, const float* sm,
                                          int b0, int tid) {
    float4* g4 = reinterpret_cast<float4*>(gp + (size_t)b0 * E);
    constexpr int T4 = G * E / 4;
#pragma unroll
    for (int i = tid; i < T4; i += TPB) {
        int e = i * 4;
        g4[i] = *reinterpret_cast<const float4*>(sm + (e / E) * S + (e % E));
    }
}

__device__ __forceinline__ void ld_row8(float* d, const float* s) {
    float4 a = *reinterpret_cast<const float4*>(s);
    float4 b = *reinterpret_cast<const float4*>(s + 4);
    d[0]=a.x; d[1]=a.y; d[2]=a.z; d[3]=a.w;
    d[4]=b.x; d[5]=b.y; d[6]=b.z; d[7]=b.w;
}
__device__ __forceinline__ void st_row8(float* d, const float* s) {
    *reinterpret_cast<float4*>(d)     = make_float4(s[0], s[1], s[2], s[3]);
    *reinterpret_cast<float4*>(d + 4) = make_float4(s[4], s[5], s[6], s[7]);
}

__global__ __launch_bounds__(TPB, 6) void kf_kernel(
    const float* __restrict__ gx, const float* __restrict__ gP,
    const float* __restrict__ gF, const float* __restrict__ gQ,
    const float* __restrict__ gz, const float* __restrict__ gH,
    const float* __restrict__ gR, float* __restrict__ out)
{
    __shared__ __align__(16) float sm[8704];   // 34.8 KB
    float* sF  = sm;               // G*68 = 2176   (P_new out)
    float* sP  = sm + 2176;        // 2176
    float* sQ  = sm + 4352;        // 2176  (scratch after Q dead: A|S|XP|y)
    float* sH  = sm + 6528;        // G*36 = 1152   (K out)
    float* sR  = sm + 7680;        // G*20 = 640
    float* sxz = sm + 8320;        // G*12 = 384  [0..7]=x, [8..11]=z  (x_new out)

    const int tid = threadIdx.x;
    const int b0  = blockIdx.x * G;
    const int g   = tid >> 1;
    const int s   = tid & 1;

    stage_in<64, SF>(sF, gF, b0, tid);
    stage_in<8, SXZ>(sxz, gx, b0, tid);
    stage_in<4, SXZ>(sxz + 8, gz, b0, tid);
    stage_in<64, SF>(sP, gP, b0, tid);
    stage_in<64, SF>(sQ, gQ, b0, tid);
    stage_in<32, SH>(sH, gH, b0, tid);
    stage_in<16, SR>(sR, gR, b0, tid);
    __syncthreads();

    float* Fb  = sF  + g * SF;
    float* Pb  = sP  + g * SF;
    float* Qb  = sQ  + g * SF;
    float* Hb  = sH  + g * SH;
    float* Rb  = sR  + g * SR;
    float* xzb = sxz + g * SXZ;
    float* Ab  = Qb;               // A [8][4] (row r at +4r), overlays dead Q
    float* Sb  = Qb + 36;          // S [4][4]
    float* XPb = Qb + 52;          // x_pred [8]
    float* Yb  = Qb + 60;          // y [4]

    // ---- own F rows (r = s + 2i); x_pred own rows ----
    float f[4][8];
#pragma unroll
    for (int i = 0; i < 4; ++i) ld_row8(f[i], Fb + (s + 2*i) * 8);
    float xv[8];
    ld_row8(xv, xzb);
    float xp[4];
#pragma unroll
    for (int i = 0; i < 4; ++i) {
        float u = 0.f;
#pragma unroll
        for (int j = 0; j < 8; ++j) u += f[i][j] * xv[j];
        xp[i] = u;
    }

    // ---- T rows: T[r][:] = sum_k F[r][k] * P[k][:] ----
    float t[4][8];
#pragma unroll
    for (int i = 0; i < 4; ++i)
#pragma unroll
        for (int j = 0; j < 8; ++j) t[i][j] = 0.f;
#pragma unroll
    for (int k = 0; k < 8; ++k) {
        float pr[8];
        ld_row8(pr, Pb + k * 8);
#pragma unroll
        for (int i = 0; i < 4; ++i) {
            float fk = f[i][k];
#pragma unroll
            for (int j = 0; j < 8; ++j) t[i][j] += fk * pr[j];
        }
    }

    // ---- P_pred rows: pp[i] = Q[own row] + T[i] . F[j][:]^T ----
    float pp[4][8];
#pragma unroll
    for (int i = 0; i < 4; ++i) ld_row8(pp[i], Qb + (s + 2*i) * 8);
#pragma unroll
    for (int j = 0; j < 8; ++j) {
        float fr[8];
        ld_row8(fr, Fb + j * 8);
#pragma unroll
        for (int i = 0; i < 4; ++i) {
            float u = pp[i][j];
#pragma unroll
            for (int k = 0; k < 8; ++k) u += t[i][k] * fr[k];
            pp[i][j] = u;
        }
    }

    // ---- A rows: A[r][m] = pp[r] . H[m] ----
    float a[4][4];
#pragma unroll
    for (int m = 0; m < 4; ++m) {
        float hr[8];
        ld_row8(hr, Hb + m * 8);
#pragma unroll
        for (int i = 0; i < 4; ++i) {
            float u = 0.f;
#pragma unroll
            for (int j = 0; j < 8; ++j) u += pp[i][j] * hr[j];
            a[i][m] = u;
        }
    }

    // ---- publish A (overlay Q) + x_pred ----
    __syncwarp();                  // partner done reading Qb/Pb/Fb cols
#pragma unroll
    for (int i = 0; i < 4; ++i)
        *reinterpret_cast<float4*>(Ab + (s + 2*i) * 4) =
            make_float4(a[i][0], a[i][1], a[i][2], a[i][3]);
#pragma unroll
    for (int i = 0; i < 4; ++i) XPb[s + 2*i] = xp[i];
    __syncwarp();                  // publish

    // ---- gather full A into regs (reused for S and P_new) ----
    float af[32];
#pragma unroll
    for (int r = 0; r < 8; ++r) {
        float4 ar = *reinterpret_cast<const float4*>(Ab + r * 4);
        af[r*4+0]=ar.x; af[r*4+1]=ar.y; af[r*4+2]=ar.z; af[r*4+3]=ar.w;
    }
    float xpv[8];
    ld_row8(xpv, XPb);

    // ---- S rows {2s, 2s+1}; y rows {2s, 2s+1} ----
#pragma unroll
    for (int mi = 0; mi < 2; ++mi) {
        int m = 2*s + mi;
        float hm[8];
        ld_row8(hm, Hb + m * 8);
        float4 rr = *reinterpret_cast<const float4*>(Rb + m * 4);
        float c0 = rr.x, c1 = rr.y, c2 = rr.z, c3 = rr.w;
        if (m == 0) c0 += EPS; else if (m == 1) c1 += EPS;
        else if (m == 2) c2 += EPS; else c3 += EPS;
        float yacc = xzb[8 + m];
#pragma unroll
        for (int i = 0; i < 8; ++i) {
            float hi = hm[i];
            c0 += hi * af[i*4+0]; c1 += hi * af[i*4+1];
            c2 += hi * af[i*4+2]; c3 += hi * af[i*4+3];
            yacc -= hi * xpv[i];
        }
        *reinterpret_cast<float4*>(Sb + m * 4) = make_float4(c0, c1, c2, c3);
        Yb[m] = yacc;
    }
    __syncwarp();                  // publish S + y

    // ---- Cholesky of S (redundant per thread) ----
    float4 S0 = *reinterpret_cast<const float4*>(Sb);
    float4 S1 = *reinterpret_cast<const float4*>(Sb + 4);
    float4 S2 = *reinterpret_cast<const float4*>(Sb + 8);
    float4 S3 = *reinterpret_cast<const float4*>(Sb + 12);
    float4 yv = *reinterpret_cast<const float4*>(Yb);
    float y[4] = {yv.x, yv.y, yv.z, yv.w};

    float iL00 = rsqrtf(S0.x);
    float L10 = S1.x * iL00, L20 = S2.x * iL00, L30 = S3.x * iL00;
    float iL11 = rsqrtf(S1.y - L10*L10);
    float L21 = (S2.y - L20*L10) * iL11;
    float L31 = (S3.y - L30*L10) * iL11;
    float iL22 = rsqrtf(S2.z - L20*L20 - L21*L21);
    float L32 = (S3.z - L30*L20 - L31*L21) * iL22;
    float iL33 = rsqrtf(S3.w - L30*L30 - L31*L31 - L32*L32);

    // ---- K rows (own): solve S k = a[i] ----
    float kk[4][4];
#pragma unroll
    for (int i = 0; i < 4; ++i) {
        float w0 = a[i][0] * iL00;
        float w1 = (a[i][1] - L10*w0) * iL11;
        float w2 = (a[i][2] - L20*w0 - L21*w1) * iL22;
        float w3 = (a[i][3] - L30*w0 - L31*w1 - L32*w2) * iL33;
        float k3 = w3 * iL33;
        float k2 = (w2 - L32*k3) * iL22;
        float k1 = (w1 - L21*k2 - L31*k3) * iL11;
        float k0 = (w0 - L10*k1 - L20*k2 - L30*k3) * iL00;
        kk[i][0]=k0; kk[i][1]=k1; kk[i][2]=k2; kk[i][3]=k3;
    }

    // ---- x_new own rows ----
    float xn[4];
#pragma unroll
    for (int i = 0; i < 4; ++i) {
        float u = xp[i];
#pragma unroll
        for (int m = 0; m < 4; ++m) u += kk[i][m] * y[m];
        xn[i] = u;
    }

    // ---- P_new rows: pn[i][j] = pp[i][j] - K[i] . A[j]  (HP = A^T) ----
    // ---- stores: P_new -> sF (F dead), x_new -> sxz, K -> sH (H dead) ----
#pragma unroll
    for (int i = 0; i < 4; ++i) {
        float pn[8];
#pragma unroll
        for (int j = 0; j < 8; ++j) {
            pn[j] = pp[i][j] - (kk[i][0]*af[j*4+0] + kk[i][1]*af[j*4+1] +
                                kk[i][2]*af[j*4+2] + kk[i][3]*af[j*4+3]);
        }
        st_row8(Fb + (s + 2*i) * 8, pn);
        *reinterpret_cast<float4*>(Hb + (s + 2*i) * 4) =
            make_float4(kk[i][0], kk[i][1], kk[i][2], kk[i][3]);
        xzb[s + 2*i] = xn[i];
    }

    __syncthreads();
    stage_out<8, SXZ>(out, sxz, b0, tid);
    stage_out<64, SF>(out + (size_t)8 * BT, sF, b0, tid);
    stage_out<32, SH>(out + (size_t)72 * BT, sH, b0, tid);
}

extern "C" void kernel_launch(void* const* d_in, const int* in_sizes, int n_in,
                              void* d_out, int out_size) {
    const float* x_est = (const float*)d_in[0];
    const float* P_est = (const float*)d_in[1];
    const float* F     = (const float*)d_in[2];
    const float* Q     = (const float*)d_in[3];
    const float* z     = (const float*)d_in[4];
    const float* H     = (const float*)d_in[5];
    const float* R     = (const float*)d_in[6];
    float* out = (float*)d_out;

    kf_kernel<<<BT / G, TPB>>>(x_est, P_est, F, Q, z, H, R, out);
}

// round 8
// speedup vs baseline: 1.2291x; 1.2291x over previous
#include <cuda_runtime.h>

// Batched Kalman filter: B=262144, N=8, M=4, fp32.
// 2 threads per batch; thread s (= tid&1) owns rows {s, s+2, s+4, s+6}.
// F, P, H, x staged through smem (coalesced float4); Q, R, z loaded directly
// per-thread (sector-clean). Pair exchange via smem + __syncwarp.
// Uses P_pred symmetry (HP = A^T). Outputs: x_new[B,8], P_new[B,8,8], K[B,8,4].

constexpr int BT  = 262144;
constexpr int TPB = 64;
constexpr int G   = 32;          // batches per block
constexpr float EPS = 1e-6f;

constexpr int SF = 68;           // 64-float mats, padded
constexpr int SH = 36;           // 32-float mats
constexpr int SX = 12;           // 8-float vecs

template<int E, int S>
__device__ __forceinline__ void stage_in(float* sm, const float* __restrict__ gp,
                                         int b0, int tid) {
    const float4* g4 = reinterpret_cast<const float4*>(gp + (size_t)b0 * E);
    constexpr int T4 = G * E / 4;
#pragma unroll
    for (int i = tid; i < T4; i += TPB) {
        float4 v = g4[i];
        int e = i * 4;
        *reinterpret_cast<float4*>(sm + (e / E) * S + (e % E)) = v;
    }
}

template<int E, int S>
__device__ __forceinline__ void stage_out(float* __restrict__ gp, const float* sm,
                                          int b0, int tid) {
    float4* g4 = reinterpret_cast<float4*>(gp + (size_t)b0 * E);
    constexpr int T4 = G * E / 4;
#pragma unroll
    for (int i = tid; i < T4; i += TPB) {
        int e = i * 4;
        g4[i] = *reinterpret_cast<const float4*>(sm + (e / E) * S + (e % E));
    }
}

__device__ __forceinline__ void ld_row8(float* d, const float* s) {
    float4 a = *reinterpret_cast<const float4*>(s);
    float4 b = *reinterpret_cast<const float4*>(s + 4);
    d[0]=a.x; d[1]=a.y; d[2]=a.z; d[3]=a.w;
    d[4]=b.x; d[5]=b.y; d[6]=b.z; d[7]=b.w;
}
__device__ __forceinline__ void st_row8(float* d, const float* s) {
    *reinterpret_cast<float4*>(d)     = make_float4(s[0], s[1], s[2], s[3]);
    *reinterpret_cast<float4*>(d + 4) = make_float4(s[4], s[5], s[6], s[7]);
}

__global__ __launch_bounds__(TPB, 8) void kf_kernel(
    const float* __restrict__ gx, const float* __restrict__ gP,
    const float* __restrict__ gF, const float* __restrict__ gQ,
    const float* __restrict__ gz, const float* __restrict__ gH,
    const float* __restrict__ gR, float* __restrict__ out)
{
    __shared__ __align__(16) float sm[5888];   // 23.6 KB
    float* sF = sm;                // G*68 = 2176  (P_new out)
    float* sP = sm + 2176;         // 2176  (scratch A|S|XP|y after P dead)
    float* sH = sm + 4352;         // G*36 = 1152  (K out)
    float* sx = sm + 5504;         // G*12 = 384   (x_new out)

    const int tid = threadIdx.x;
    const int b0  = blockIdx.x * G;
    const int g   = tid >> 1;
    const int s   = tid & 1;
    const size_t gb = (size_t)(b0 + g);

    // ---- direct per-thread loads (issued early; sector-clean) ----
    float4 r4a = *reinterpret_cast<const float4*>(gR + gb * 16 + (2*s) * 4);
    float4 r4b = *reinterpret_cast<const float4*>(gR + gb * 16 + (2*s + 1) * 4);
    float z2a = gz[gb * 4 + 2*s];
    float z2b = gz[gb * 4 + 2*s + 1];

    stage_in<64, SF>(sF, gF, b0, tid);
    stage_in<64, SF>(sP, gP, b0, tid);
    stage_in<32, SH>(sH, gH, b0, tid);
    stage_in<8, SX>(sx, gx, b0, tid);
    __syncthreads();

    float* Fb = sF + g * SF;
    float* Pb = sP + g * SF;
    float* Hb = sH + g * SH;
    float* xb = sx + g * SX;
    float* Ab  = Pb;               // A [8][4] (row r at +4r) after P dead
    float* Sb  = Pb + 36;          // S [4][4]
    float* XPb = Pb + 52;          // x_pred [8]
    float* Yb  = Pb + 60;          // y [4]

    // ---- own F rows (r = s + 2i); x_pred own rows ----
    float f[4][8];
#pragma unroll
    for (int i = 0; i < 4; ++i) ld_row8(f[i], Fb + (s + 2*i) * 8);
    float xv[8];
    ld_row8(xv, xb);
    float xp[4];
#pragma unroll
    for (int i = 0; i < 4; ++i) {
        float u = 0.f;
#pragma unroll
        for (int j = 0; j < 8; ++j) u += f[i][j] * xv[j];
        xp[i] = u;
    }

    // ---- pp init = own Q rows (direct gmem, early issue) ----
    float pp[4][8];
#pragma unroll
    for (int i = 0; i < 4; ++i)
        ld_row8(pp[i], gQ + gb * 64 + (s + 2*i) * 8);

    // ---- T rows: T[r][:] = sum_k F[r][k] * P[k][:] ----
    float t[4][8];
#pragma unroll
    for (int i = 0; i < 4; ++i)
#pragma unroll
        for (int j = 0; j < 8; ++j) t[i][j] = 0.f;
#pragma unroll
    for (int k = 0; k < 8; ++k) {
        float pr[8];
        ld_row8(pr, Pb + k * 8);
#pragma unroll
        for (int i = 0; i < 4; ++i) {
            float fk = f[i][k];
#pragma unroll
            for (int j = 0; j < 8; ++j) t[i][j] += fk * pr[j];
        }
    }

    // ---- P_pred rows: pp[i][j] += T[i] . F[j][:] ----
#pragma unroll
    for (int j = 0; j < 8; ++j) {
        float fr[8];
        ld_row8(fr, Fb + j * 8);
#pragma unroll
        for (int i = 0; i < 4; ++i) {
            float u = pp[i][j];
#pragma unroll
            for (int k = 0; k < 8; ++k) u += t[i][k] * fr[k];
            pp[i][j] = u;
        }
    }

    // ---- A rows: A[r][m] = pp[r] . H[m] ----
    float a[4][4];
#pragma unroll
    for (int m = 0; m < 4; ++m) {
        float hr[8];
        ld_row8(hr, Hb + m * 8);
#pragma unroll
        for (int i = 0; i < 4; ++i) {
            float u = 0.f;
#pragma unroll
            for (int j = 0; j < 8; ++j) u += pp[i][j] * hr[j];
            a[i][m] = u;
        }
    }

    // ---- publish A (overlay dead P) + x_pred ----
    __syncwarp();                  // pair done reading Pb
#pragma unroll
    for (int i = 0; i < 4; ++i)
        *reinterpret_cast<float4*>(Ab + (s + 2*i) * 4) =
            make_float4(a[i][0], a[i][1], a[i][2], a[i][3]);
#pragma unroll
    for (int i = 0; i < 4; ++i) XPb[s + 2*i] = xp[i];
    __syncwarp();                  // publish

    // ---- gather full A into regs (reused for S and P_new) ----
    float af[32];
#pragma unroll
    for (int r = 0; r < 8; ++r) {
        float4 ar = *reinterpret_cast<const float4*>(Ab + r * 4);
        af[r*4+0]=ar.x; af[r*4+1]=ar.y; af[r*4+2]=ar.z; af[r*4+3]=ar.w;
    }
    float xpv[8];
    ld_row8(xpv, XPb);

    // ---- S rows {2s, 2s+1} (R direct) ; y rows {2s, 2s+1} (z direct) ----
#pragma unroll
    for (int mi = 0; mi < 2; ++mi) {
        int m = 2*s + mi;
        float hm[8];
        ld_row8(hm, Hb + m * 8);
        float4 rr = (mi == 0) ? r4a : r4b;
        float c0 = rr.x, c1 = rr.y, c2 = rr.z, c3 = rr.w;
        if (m == 0) c0 += EPS; else if (m == 1) c1 += EPS;
        else if (m == 2) c2 += EPS; else c3 += EPS;
        float yacc = (mi == 0) ? z2a : z2b;
#pragma unroll
        for (int i = 0; i < 8; ++i) {
            float hi = hm[i];
            c0 += hi * af[i*4+0]; c1 += hi * af[i*4+1];
            c2 += hi * af[i*4+2]; c3 += hi * af[i*4+3];
            yacc -= hi * xpv[i];
        }
        *reinterpret_cast<float4*>(Sb + m * 4) = make_float4(c0, c1, c2, c3);
        Yb[m] = yacc;
    }
    __syncwarp();                  // publish S + y; also last Hb read done

    // ---- Cholesky of S (redundant per thread) ----
    float4 S0 = *reinterpret_cast<const float4*>(Sb);
    float4 S1 = *reinterpret_cast<const float4*>(Sb + 4);
    float4 S2 = *reinterpret_cast<const float4*>(Sb + 8);
    float4 S3 = *reinterpret_cast<const float4*>(Sb + 12);
    float4 yv = *reinterpret_cast<const float4*>(Yb);
    float y[4] = {yv.x, yv.y, yv.z, yv.w};

    float iL00 = rsqrtf(S0.x);
    float L10 = S1.x * iL00, L20 = S2.x * iL00, L30 = S3.x * iL00;
    float iL11 = rsqrtf(S1.y - L10*L10);
    float L21 = (S2.y - L20*L10) * iL11;
    float L31 = (S3.y - L30*L10) * iL11;
    float iL22 = rsqrtf(S2.z - L20*L20 - L21*L21);
    float L32 = (S3.z - L30*L20 - L31*L21) * iL22;
    float iL33 = rsqrtf(S3.w - L30*L30 - L31*L31 - L32*L32);

    // ---- K rows (own): solve S k = a[i]; x_new; P_new; stores ----
#pragma unroll
    for (int i = 0; i < 4; ++i) {
        float w0 = a[i][0] * iL00;
        float w1 = (a[i][1] - L10*w0) * iL11;
        float w2 = (a[i][2] - L20*w0 - L21*w1) * iL22;
        float w3 = (a[i][3] - L30*w0 - L31*w1 - L32*w2) * iL33;
        float k3 = w3 * iL33;
        float k2 = (w2 - L32*k3) * iL22;
        float k1 = (w1 - L21*k2 - L31*k3) * iL11;
        float k0 = (w0 - L10*k1 - L20*k2 - L30*k3) * iL00;

        float xn = xp[i] + k0*y[0] + k1*y[1] + k2*y[2] + k3*y[3];

        float pn[8];
#pragma unroll
        for (int j = 0; j < 8; ++j)
            pn[j] = pp[i][j] - (k0*af[j*4+0] + k1*af[j*4+1] +
                                k2*af[j*4+2] + k3*af[j*4+3]);

        st_row8(Fb + (s + 2*i) * 8, pn);                         // P_new -> sF
        *reinterpret_cast<float4*>(Hb + (s + 2*i) * 4) =
            make_float4(k0, k1, k2, k3);                         // K -> sH
        xb[s + 2*i] = xn;                                        // x_new -> sx
    }

    __syncthreads();
    stage_out<8, SX>(out, sx, b0, tid);
    stage_out<64, SF>(out + (size_t)8 * BT, sF, b0, tid);
    stage_out<32, SH>(out + (size_t)72 * BT, sH, b0, tid);
}

extern "C" void kernel_launch(void* const* d_in, const int* in_sizes, int n_in,
                              void* d_out, int out_size) {
    const float* x_est = (const float*)d_in[0];
    const float* P_est = (const float*)d_in[1];
    const float* F     = (const float*)d_in[2];
    const float* Q     = (const float*)d_in[3];
    const float* z     = (const float*)d_in[4];
    const float* H     = (const float*)d_in[5];
    const float* R     = (const float*)d_in[6];
    float* out = (float*)d_out;

    kf_kernel<<<BT / G, TPB>>>(x_est, P_est, F, Q, z, H, R, out);
}